// round 5
// baseline (speedup 1.0000x reference)
#include <cuda_runtime.h>

// Butterfly multiply: BATCH=16384 rows, N=2048, 11 stages, increasing stride.
// One CTA = 256 threads processes 8 rows (4 f32x2-packed row pairs).
// Stage strides 1..4 intra-thread, 8..128 via shfl.xor, one swizzled smem
// transpose, strides 256..1024 intra-thread, bias folded into last stage.
//
// Packed f32x2 values are carried in unsigned long long ("l" asm constraint).

typedef unsigned long long u64;

__device__ __forceinline__ u64 d_fma2(u64 a, u64 b, u64 c) {
    u64 d; asm("fma.rn.f32x2 %0, %1, %2, %3;" : "=l"(d) : "l"(a), "l"(b), "l"(c)); return d;
}
__device__ __forceinline__ u64 d_mul2(u64 a, u64 b) {
    u64 d; asm("mul.rn.f32x2 %0, %1, %2;" : "=l"(d) : "l"(a), "l"(b)); return d;
}
__device__ __forceinline__ u64 d_bcast(float x) {
    unsigned u = __float_as_uint(x);
    u64 d; asm("mov.b64 %0, {%1, %1};" : "=l"(d) : "r"(u)); return d;
}
__device__ __forceinline__ u64 d_pack(float lo, float hi) {
    u64 d; asm("mov.b64 %0, {%1, %2};" : "=l"(d)
               : "r"(__float_as_uint(lo)), "r"(__float_as_uint(hi))); return d;
}
__device__ __forceinline__ float d_lo(u64 v) { return __uint_as_float((unsigned)(v & 0xffffffffu)); }
__device__ __forceinline__ float d_hi(u64 v) { return __uint_as_float((unsigned)(v >> 32)); }

__global__ __launch_bounds__(256, 2)
void butterfly_kernel(const float* __restrict__ x,
                      const float* __restrict__ tw,
                      const float* __restrict__ bias,
                      float* __restrict__ out)
{
    __shared__ u64 buf[2048];   // 16 KB transpose buffer (reused per row-pair)
    const int t = threadIdx.x;
    const long long row0 = (long long)blockIdx.x * 8;

    u64 v[4][8];

    // ---- Load 8 rows, elements 8t..8t+7, packed as (even row, odd row) f32x2 ----
    #pragma unroll
    for (int p = 0; p < 4; ++p) {
        const float4* ra = reinterpret_cast<const float4*>(x + (row0 + 2*p)     * 2048 + 8*t);
        const float4* rb = reinterpret_cast<const float4*>(x + (row0 + 2*p + 1) * 2048 + 8*t);
        float4 a0 = ra[0], a1 = ra[1];
        float4 b0 = rb[0], b1 = rb[1];
        v[p][0] = d_pack(a0.x, b0.x); v[p][1] = d_pack(a0.y, b0.y);
        v[p][2] = d_pack(a0.z, b0.z); v[p][3] = d_pack(a0.w, b0.w);
        v[p][4] = d_pack(a1.x, b1.x); v[p][5] = d_pack(a1.y, b1.y);
        v[p][6] = d_pack(a1.z, b1.z); v[p][7] = d_pack(a1.w, b1.w);
    }

    // ---- Bias for final column ownership c = t + 256k ----
    u64 bpk[8];
    #pragma unroll
    for (int k = 0; k < 8; ++k) bpk[k] = d_bcast(bias[t + 256*k]);

    // ---- Phase A: stages 0..2 (s=1,2,4), intra-thread, ownership e = 8t+j ----
    #pragma unroll
    for (int idx = 0; idx < 3; ++idx) {
        const int s = 1 << idx;
        #pragma unroll
        for (int j = 0; j < 8; ++j) {
            if ((j >> idx) & 1) continue;           // j is lo-side only
            const int e = 8*t + j;
            const int w = (e >> (idx + 1)) * s + (e & (s - 1));
            const float4 T = *reinterpret_cast<const float4*>(tw + ((idx << 10) + w) * 4);
            const u64 T00 = d_bcast(T.x), T01 = d_bcast(T.y);
            const u64 T10 = d_bcast(T.z), T11 = d_bcast(T.w);
            #pragma unroll
            for (int p = 0; p < 4; ++p) {
                const u64 lo = v[p][j], hi = v[p][j + s];
                v[p][j]     = d_fma2(T00, lo, d_mul2(T01, hi));
                v[p][j + s] = d_fma2(T10, lo, d_mul2(T11, hi));
            }
        }
    }

    // ---- Phase B: stages 3..7 (s=8..128), partner thread = t ^ (s/8), shfl.xor ----
    #pragma unroll
    for (int idx = 3; idx < 8; ++idx) {
        const int s = 1 << idx;
        const int m = 1 << (idx - 3);
        const int side = (t >> (idx - 3)) & 1;      // 0 = lo half, 1 = hi half
        #pragma unroll
        for (int j = 0; j < 8; ++j) {
            const int e = 8*t + j;
            const int w = (e >> (idx + 1)) * s + (e & (s - 1));
            // row `side` of the 2x2: (T[side][0], T[side][1]) -> one LDG.64
            const float2 T = *reinterpret_cast<const float2*>(
                tw + ((idx << 10) + w) * 4 + side * 2);
            const u64 Ta = d_bcast(T.x), Tb = d_bcast(T.y);
            #pragma unroll
            for (int p = 0; p < 4; ++p) {
                const u64 mine = v[p][j];
                const u64 part = __shfl_xor_sync(0xffffffffu, mine, m);
                const u64 xlo = side ? part : mine;
                const u64 xhi = side ? mine : part;
                v[p][j] = d_fma2(Ta, xlo, d_mul2(Tb, xhi));
            }
        }
    }

    // ---- Transpose: ownership 8t+j  ->  t + 256k  (swizzled, conflict-free) ----
    // store: value j goes to phys = 8t + (j ^ ((t>>1)&7))
    // load:  element t+256k sits at  phys = 8*((t>>3)+32k) + ((t&7) ^ ((t>>4)&7))
    const int ps = (t >> 1) & 7;
    const int jr = (t & 7) ^ ((t >> 4) & 7);
    #pragma unroll
    for (int p = 0; p < 4; ++p) {
        if (p) __syncthreads();                     // protect buf reuse
        #pragma unroll
        for (int j = 0; j < 8; ++j) buf[8*t + (j ^ ps)] = v[p][j];
        __syncthreads();
        #pragma unroll
        for (int k = 0; k < 8; ++k) v[p][k] = buf[8*((t >> 3) + 32*k) + jr];
    }

    // ---- Phase C: stages 8..10 (s=256,512,1024), intra-thread on k ----
    #pragma unroll
    for (int idx = 8; idx < 11; ++idx) {
        const int s = 1 << idx;
        const int m = 1 << (idx - 8);
        const bool last = (idx == 10);
        #pragma unroll
        for (int k = 0; k < 8; ++k) {
            if ((k >> (idx - 8)) & 1) continue;     // k is lo-side only
            const int e = t + 256*k;
            const int w = (e >> (idx + 1)) * s + (e & (s - 1));
            const float4 T = *reinterpret_cast<const float4*>(tw + ((idx << 10) + w) * 4);
            const u64 T00 = d_bcast(T.x), T01 = d_bcast(T.y);
            const u64 T10 = d_bcast(T.z), T11 = d_bcast(T.w);
            #pragma unroll
            for (int p = 0; p < 4; ++p) {
                const u64 lo = v[p][k], hi = v[p][k + m];
                if (last) {   // fold bias into the last stage (zero extra ops)
                    v[p][k]     = d_fma2(T00, lo, d_fma2(T01, hi, bpk[k]));
                    v[p][k + m] = d_fma2(T10, lo, d_fma2(T11, hi, bpk[k + m]));
                } else {
                    v[p][k]     = d_fma2(T00, lo, d_mul2(T01, hi));
                    v[p][k + m] = d_fma2(T10, lo, d_mul2(T11, hi));
                }
            }
        }
    }

    // ---- Store: column c = t + 256k; warp writes 32 consecutive floats ----
    #pragma unroll
    for (int p = 0; p < 4; ++p) {
        float* oa = out + (row0 + 2*p)     * 2048;
        float* ob = out + (row0 + 2*p + 1) * 2048;
        #pragma unroll
        for (int k = 0; k < 8; ++k) {
            oa[t + 256*k] = d_lo(v[p][k]);
            ob[t + 256*k] = d_hi(v[p][k]);
        }
    }
}

extern "C" void kernel_launch(void* const* d_in, const int* in_sizes, int n_in,
                              void* d_out, int out_size)
{
    const float* x    = (const float*)d_in[0];
    const float* tw   = (const float*)d_in[1];
    const float* bias = (const float*)d_in[2];
    float* out        = (float*)d_out;

    const int rows = in_sizes[0] / 2048;   // 16384
    butterfly_kernel<<<rows / 8, 256>>>(x, tw, bias, out);
}

// round 6
// speedup vs baseline: 1.4052x; 1.4052x over previous
#include <cuda_runtime.h>

// Butterfly multiply: 16384 rows, N=2048, 11 stages, increasing stride.
// CTA = 256 threads, 8 rows (4 f32x2-packed row pairs).
// Ownership ladder (all butterflies intra-thread, all twiddle loads coalesced):
//   G0: e = 8t+j          stages 0-2   (twiddle via repacked scratch, coalesced)
//   G1: e = 64a+b+8j      stages 3-5   (twiddle naturally coalesced)
//   G2: e = 512c+d+64j    stages 6-8   (coalesced)
//   G3: e = t+256j        stages 9-10  (coalesced, bias folded into stage 10)
// Three smem transposes with XOR swizzle phys=(e>>1)^H(e>>4), conflict-free
// for every access pattern used.

typedef unsigned long long u64;

__device__ float4 g_rp[3072];   // repacked twiddles for stages 0-2 (48 KB)

__device__ __forceinline__ u64 d_fma2(u64 a, u64 b, u64 c) {
    u64 d; asm("fma.rn.f32x2 %0, %1, %2, %3;" : "=l"(d) : "l"(a), "l"(b), "l"(c)); return d;
}
__device__ __forceinline__ u64 d_mul2(u64 a, u64 b) {
    u64 d; asm("mul.rn.f32x2 %0, %1, %2;" : "=l"(d) : "l"(a), "l"(b)); return d;
}
__device__ __forceinline__ u64 d_bcast(float x) {
    unsigned u = __float_as_uint(x);
    u64 d; asm("mov.b64 %0, {%1, %1};" : "=l"(d) : "r"(u)); return d;
}
__device__ __forceinline__ u64 d_pack(float lo, float hi) {
    u64 d; asm("mov.b64 %0, {%1, %2};" : "=l"(d)
               : "r"(__float_as_uint(lo)), "r"(__float_as_uint(hi))); return d;
}
__device__ __forceinline__ float d_lo(u64 v) { return __uint_as_float((unsigned)(v & 0xffffffffu)); }
__device__ __forceinline__ float d_hi(u64 v) { return __uint_as_float((unsigned)(v >> 32)); }

__device__ __forceinline__ int H(int u) { return (u & 3) | (((u >> 2) & 1) << 2); }

// Repack stage 0-2 twiddle entries into lane-major order:
// g_rp[(idx*4 + i)*256 + t] = tw4[idx*1024 + 4t + i]
__global__ void repack_kernel(const float4* __restrict__ tw4) {
    int dst = blockIdx.x * 256 + threadIdx.x;          // 0..3071
    int idx = dst >> 10, r = dst & 1023, i = r >> 8, t = r & 255;
    g_rp[dst] = tw4[idx * 1024 + 4 * t + i];
}

__global__ __launch_bounds__(256, 2)
void butterfly_kernel(const float* __restrict__ x,
                      const float* __restrict__ tw,
                      const float* __restrict__ bias,
                      float* __restrict__ out)
{
    __shared__ u64 buf[2][2048];                 // 32 KB: 2 row-pairs at a time
    const int t = threadIdx.x;
    const int a = t >> 3, b = t & 7;             // G1 coords
    const int c = t >> 6, d = t & 63;            // G2 coords
    const long long row0 = (long long)blockIdx.x * 8;
    const float4* tw4 = reinterpret_cast<const float4*>(tw);

    u64 v[4][8];

    // ---- Load 8 rows, elements 8t..8t+7 packed (even,odd) rows into f32x2 ----
    #pragma unroll
    for (int p = 0; p < 4; ++p) {
        const float4* ra = reinterpret_cast<const float4*>(x + (row0 + 2*p)     * 2048 + 8*t);
        const float4* rb = reinterpret_cast<const float4*>(x + (row0 + 2*p + 1) * 2048 + 8*t);
        float4 a0 = ra[0], a1 = ra[1], b0 = rb[0], b1 = rb[1];
        v[p][0] = d_pack(a0.x, b0.x); v[p][1] = d_pack(a0.y, b0.y);
        v[p][2] = d_pack(a0.z, b0.z); v[p][3] = d_pack(a0.w, b0.w);
        v[p][4] = d_pack(a1.x, b1.x); v[p][5] = d_pack(a1.y, b1.y);
        v[p][6] = d_pack(a1.z, b1.z); v[p][7] = d_pack(a1.w, b1.w);
    }

    // Apply one stage given 4 twiddles, 4 lo-j's and pair offset dl
    #define APPLY4(T0_, T1_, T2_, T3_, J0, J1, J2, J3, DL)                           \
    {                                                                                \
        const float4 Ts[4] = { T0_, T1_, T2_, T3_ };                                 \
        const int js[4] = { J0, J1, J2, J3 };                                        \
        _Pragma("unroll")                                                            \
        for (int q = 0; q < 4; ++q) {                                                \
            const u64 T00 = d_bcast(Ts[q].x), T01 = d_bcast(Ts[q].y);                \
            const u64 T10 = d_bcast(Ts[q].z), T11 = d_bcast(Ts[q].w);                \
            const int j = js[q];                                                     \
            _Pragma("unroll")                                                        \
            for (int p = 0; p < 4; ++p) {                                            \
                const u64 lo = v[p][j], hi = v[p][j + DL];                           \
                v[p][j]      = d_fma2(T00, lo, d_mul2(T01, hi));                     \
                v[p][j + DL] = d_fma2(T10, lo, d_mul2(T11, hi));                     \
            }                                                                        \
        }                                                                            \
    }

    // ---- G0: stages 0-2 via repacked scratch (fully coalesced) ----
    {   // stage 0: pairs (j,j+1), i = j/2
        float4 A = g_rp[(0*4+0)*256 + t], B = g_rp[(0*4+1)*256 + t],
               C = g_rp[(0*4+2)*256 + t], D = g_rp[(0*4+3)*256 + t];
        APPLY4(A, B, C, D, 0, 2, 4, 6, 1);
    }
    {   // stage 1: pairs (j,j+2), j in {0,1,4,5}, i = 2*(j>>2)+(j&1)
        float4 A = g_rp[(1*4+0)*256 + t], B = g_rp[(1*4+1)*256 + t],
               C = g_rp[(1*4+2)*256 + t], D = g_rp[(1*4+3)*256 + t];
        APPLY4(A, B, C, D, 0, 1, 4, 5, 2);
    }
    {   // stage 2: pairs (j,j+4), i = j
        float4 A = g_rp[(2*4+0)*256 + t], B = g_rp[(2*4+1)*256 + t],
               C = g_rp[(2*4+2)*256 + t], D = g_rp[(2*4+3)*256 + t];
        APPLY4(A, B, C, D, 0, 1, 2, 3, 4);
    }

    // ---- Transpose T1: G0 (8t+j) -> G1 (64a+b+8j) ----
    #pragma unroll
    for (int h = 0; h < 2; ++h) {
        __syncthreads();
        #pragma unroll
        for (int q = 0; q < 2; ++q) {           // store: 4 STS.128 per p
            const int p = 2*h + q;
            ulonglong2* B2 = reinterpret_cast<ulonglong2*>(buf[q]);
            #pragma unroll
            for (int i = 0; i < 4; ++i) {
                const int m = 4*t + i;
                B2[m ^ H(m >> 3)] = make_ulonglong2(v[p][2*i], v[p][2*i + 1]);
            }
        }
        __syncthreads();
        #pragma unroll
        for (int q = 0; q < 2; ++q) {           // load: 8 LDS.64 per p
            const int p = 2*h + q;
            #pragma unroll
            for (int j = 0; j < 8; ++j) {
                const int m = 32*a + 4*j + (b >> 1);
                v[p][j] = buf[q][2 * (m ^ H(m >> 3)) + (b & 1)];
            }
        }
    }

    // ---- G1: stages 3-5, e = 64a+b+8j (twiddle coalesced) ----
    {   // stage 3: pairs (j,j+1); w = 32a + 4j + b
        const float4* tp = tw4 + (3 << 10);
        float4 A = tp[32*a + b], B = tp[32*a + 8 + b],
               C = tp[32*a + 16 + b], D = tp[32*a + 24 + b];
        APPLY4(A, B, C, D, 0, 2, 4, 6, 1);
    }
    {   // stage 4: pairs (j,j+2), j in {0,1,4,5}; w = 32a + 16*(j>>2) + 8*(j&1) + b
        const float4* tp = tw4 + (4 << 10);
        float4 A = tp[32*a + b], B = tp[32*a + 8 + b],
               C = tp[32*a + 16 + b], D = tp[32*a + 24 + b];
        APPLY4(A, B, C, D, 0, 1, 4, 5, 2);
    }
    {   // stage 5: pairs (j,j+4); w = 32a + 8j + b
        const float4* tp = tw4 + (5 << 10);
        float4 A = tp[32*a + b], B = tp[32*a + 8 + b],
               C = tp[32*a + 16 + b], D = tp[32*a + 24 + b];
        APPLY4(A, B, C, D, 0, 1, 2, 3, 4);
    }

    // ---- Transpose T2: G1 -> G2 (512c+d+64j) ----
    #pragma unroll
    for (int h = 0; h < 2; ++h) {
        __syncthreads();
        #pragma unroll
        for (int q = 0; q < 2; ++q) {
            const int p = 2*h + q;
            #pragma unroll
            for (int j = 0; j < 8; ++j) {
                const int m = 32*a + 4*j + (b >> 1);
                buf[q][2 * (m ^ H(m >> 3)) + (b & 1)] = v[p][j];
            }
        }
        __syncthreads();
        #pragma unroll
        for (int q = 0; q < 2; ++q) {
            const int p = 2*h + q;
            #pragma unroll
            for (int j = 0; j < 8; ++j) {
                const int m = 256*c + 32*j + (d >> 1);
                v[p][j] = buf[q][2 * (m ^ H(m >> 3)) + (d & 1)];
            }
        }
    }

    // ---- G2: stages 6-8, e = 512c+d+64j (twiddle coalesced) ----
    {   // stage 6: pairs (j,j+1); w = 256c + 32j + d
        const float4* tp = tw4 + (6 << 10);
        float4 A = tp[256*c + d], B = tp[256*c + 64 + d],
               C = tp[256*c + 128 + d], D = tp[256*c + 192 + d];
        APPLY4(A, B, C, D, 0, 2, 4, 6, 1);
    }
    {   // stage 7: pairs (j,j+2), j in {0,1,4,5}; w = 256c + 128*(j>>2) + 64*(j&1) + d
        const float4* tp = tw4 + (7 << 10);
        float4 A = tp[256*c + d], B = tp[256*c + 64 + d],
               C = tp[256*c + 128 + d], D = tp[256*c + 192 + d];
        APPLY4(A, B, C, D, 0, 1, 4, 5, 2);
    }
    {   // stage 8: pairs (j,j+4); w = 256c + 64j + d
        const float4* tp = tw4 + (8 << 10);
        float4 A = tp[256*c + d], B = tp[256*c + 64 + d],
               C = tp[256*c + 128 + d], D = tp[256*c + 192 + d];
        APPLY4(A, B, C, D, 0, 1, 2, 3, 4);
    }

    // ---- Transpose T3: G2 -> G3 (t+256j) ----
    #pragma unroll
    for (int h = 0; h < 2; ++h) {
        __syncthreads();
        #pragma unroll
        for (int q = 0; q < 2; ++q) {
            const int p = 2*h + q;
            #pragma unroll
            for (int j = 0; j < 8; ++j) {
                const int m = 256*c + 32*j + (d >> 1);
                buf[q][2 * (m ^ H(m >> 3)) + (d & 1)] = v[p][j];
            }
        }
        __syncthreads();
        #pragma unroll
        for (int q = 0; q < 2; ++q) {
            const int p = 2*h + q;
            #pragma unroll
            for (int j = 0; j < 8; ++j) {
                const int m = 128*j + (t >> 1);
                v[p][j] = buf[q][2 * (m ^ H(m >> 3)) + (t & 1)];
            }
        }
    }

    // ---- Bias (coalesced) ----
    float bb[8];
    #pragma unroll
    for (int j = 0; j < 8; ++j) bb[j] = bias[t + 256*j];

    // ---- G3: stages 9-10, e = t+256j (twiddle coalesced, bias folded) ----
    {   // stage 9: pairs (j,j+2), j in {0,1,4,5}; w = 512*(j>>2) + 256*(j&1) + t
        const float4* tp = tw4 + (9 << 10);
        float4 A = tp[t], B = tp[256 + t], C = tp[512 + t], D = tp[768 + t];
        APPLY4(A, B, C, D, 0, 1, 4, 5, 2);
    }
    {   // stage 10: pairs (j,j+4); w = 256j + t; add bias
        const float4* tp = tw4 + (10 << 10);
        #pragma unroll
        for (int j = 0; j < 4; ++j) {
            const float4 T = tp[256*j + t];
            const u64 T00 = d_bcast(T.x), T01 = d_bcast(T.y);
            const u64 T10 = d_bcast(T.z), T11 = d_bcast(T.w);
            const u64 blo = d_bcast(bb[j]), bhi = d_bcast(bb[j + 4]);
            #pragma unroll
            for (int p = 0; p < 4; ++p) {
                const u64 lo = v[p][j], hi = v[p][j + 4];
                v[p][j]     = d_fma2(T00, lo, d_fma2(T01, hi, blo));
                v[p][j + 4] = d_fma2(T10, lo, d_fma2(T11, hi, bhi));
            }
        }
    }

    // ---- Store: element t+256j of each row (coalesced) ----
    #pragma unroll
    for (int p = 0; p < 4; ++p) {
        float* oa = out + (row0 + 2*p)     * 2048;
        float* ob = out + (row0 + 2*p + 1) * 2048;
        #pragma unroll
        for (int j = 0; j < 8; ++j) {
            oa[t + 256*j] = d_lo(v[p][j]);
            ob[t + 256*j] = d_hi(v[p][j]);
        }
    }
    #undef APPLY4
}

extern "C" void kernel_launch(void* const* d_in, const int* in_sizes, int n_in,
                              void* d_out, int out_size)
{
    const float* x    = (const float*)d_in[0];
    const float* tw   = (const float*)d_in[1];
    const float* bias = (const float*)d_in[2];
    float* out        = (float*)d_out;

    repack_kernel<<<12, 256>>>(reinterpret_cast<const float4*>(tw));
    const int rows = in_sizes[0] / 2048;   // 16384
    butterfly_kernel<<<rows / 8, 256>>>(x, tw, bias, out);
}